// round 11
// baseline (speedup 1.0000x reference)
#include <cuda_runtime.h>
#include <cuda_fp16.h>
#include <cstdint>
#include <cfloat>

#define DIM    512
#define NE     4096
#define NROWS  65536
#define THRESH 0.35f

// ---------------- scratch (__device__ globals) ----------------
__device__ __align__(128) __half g_Ah[(size_t)NROWS * DIM];  // x as fp16
__device__ __align__(128) __half g_Bh[(size_t)NE * DIM];     // embT as fp16
__device__ float g_embT[(size_t)NE * DIM];
__device__ float g_e2[NE];
__device__ int   g_best[NROWS];
__device__ float g_margin[NROWS];
__device__ float g_partial[NROWS];
__device__ int   g_list[NROWS];
__device__ int   g_cnt;

// ---------------- asm helpers ----------------
__device__ __forceinline__ uint32_t smem_u32(const void* p) {
    uint32_t a;
    asm("{ .reg .u64 t; cvta.to.shared.u64 t, %1; cvt.u32.u64 %0, t; }" : "=r"(a) : "l"(p));
    return a;
}
#define CP16(dst, src) \
    asm volatile("cp.async.cg.shared.global [%0], [%1], 16;" :: "r"(dst), "l"(src))
#define CP_COMMIT() asm volatile("cp.async.commit_group;" ::: "memory")

#define LDSM4(r, addr) \
    asm volatile("ldmatrix.sync.aligned.m8n8.x4.shared.b16 {%0,%1,%2,%3}, [%4];" \
        : "=r"((r)[0]), "=r"((r)[1]), "=r"((r)[2]), "=r"((r)[3]) : "r"(addr))

#define MMA16(c, a, b0, b1) \
    asm volatile("mma.sync.aligned.m16n8k16.row.col.f32.f16.f16.f32 " \
        "{%0,%1,%2,%3},{%4,%5,%6,%7},{%8,%9},{%0,%1,%2,%3};" \
        : "+f"((c)[0]), "+f"((c)[1]), "+f"((c)[2]), "+f"((c)[3]) \
        : "r"((a)[0]), "r"((a)[1]), "r"((a)[2]), "r"((a)[3]), "r"(b0), "r"(b1))

// ---------------- prep: pack x -> fp16 ----------------
__global__ __launch_bounds__(256) void pack_x_kernel(const float* __restrict__ x) {
    size_t g = (size_t)blockIdx.x * 256 + threadIdx.x;
    if (g == 0) g_cnt = 0;
    size_t e = g * 4;
    float4 v = *(const float4*)(x + e);
    __half2 h0 = __floats2half2_rn(v.x, v.y);
    __half2 h1 = __floats2half2_rn(v.z, v.w);
    uint2 pk;
    pk.x = *(uint32_t*)&h0;
    pk.y = *(uint32_t*)&h1;
    *(uint2*)(g_Ah + e) = pk;
}

// ---------------- prep: transpose embed -> fp16 B + fp32 embT ----------------
__global__ void pack_embed_kernel(const float* __restrict__ embed) {
    __shared__ float tile[32][33];
    int jb = blockIdx.x * 32;
    int db = blockIdx.y * 32;
    int tx = threadIdx.x, ty = threadIdx.y;  // 32 x 8
    #pragma unroll
    for (int d = ty; d < 32; d += 8)
        tile[d][tx] = embed[(size_t)(db + d) * NE + jb + tx];
    __syncthreads();
    #pragma unroll
    for (int j = ty; j < 32; j += 8) {
        float v = tile[tx][j];
        size_t o = (size_t)(jb + j) * DIM + db + tx;
        g_Bh[o]   = __float2half_rn(v);
        g_embT[o] = v;
    }
}

__global__ void prep_e2(const float* __restrict__ embed) {
    int j = blockIdx.x * blockDim.x + threadIdx.x;
    if (j < NE) {
        float s = 0.f;
        #pragma unroll 8
        for (int d = 0; d < DIM; d++) {
            float v = embed[(size_t)d * NE + j];
            s = fmaf(v, v, s);
        }
        g_e2[j] = s;
    }
}

// ---------------- GEMM + argmin (mma.sync fp16, 512 threads) --------
// SMEM layout (dynamic, 212992 B):
//   [0, 131072)        A block 128 x 512 fp16, swizzled
//   [131072, 196608)   B stages: 4 x 16384 (128n x 64k fp16, swizzled)
//                      (reused post-loop as merge buffer)
//   [196608, 212992)   e2[4096] fp32
#define SA_OFF 0
#define SB_OFF 131072
#define SE_OFF 196608
#define SMEM_SZ 212992
#define NT 512

__device__ __forceinline__ void load_B(uint32_t sB, int t, int slot, int idx) {
    const int col0 = (idx >> 3) << 7;
    const int kk = idx & 7;
    const __half* base = g_Bh + (size_t)col0 * DIM + kk * 64;
    uint32_t sbase = sB + slot * 16384;
    #pragma unroll
    for (int i = 0; i < 2; i++) {
        int q = t + i * NT;
        int n = q >> 3, ck = q & 7;
        uint32_t dst = sbase + n * 128 + (((ck ^ (n & 7))) << 4);
        const __half* src = base + (size_t)n * DIM + ck * 8;
        CP16(dst, src);
    }
}

__global__ __launch_bounds__(NT, 1) void gemm_argmin_kernel() {
    extern __shared__ __align__(128) char smem[];
    const uint32_t sbase = smem_u32(smem);
    const uint32_t sA = sbase + SA_OFF;
    const uint32_t sB = sbase + SB_OFF;
    const int t = threadIdx.x;
    const int lane = t & 31, warp = t >> 5;
    const int wr = warp >> 2, wc = warp & 3;      // 4 x 4 warp grid
    const int row0 = blockIdx.x * 128;
    float* e2p = (float*)(smem + SE_OFF);

    // ---- group 0: A block (128x512 fp16) + e2 ----
    #pragma unroll
    for (int i = 0; i < 16; i++) {
        int q = t + i * NT;           // 8192 16B chunks
        int r = q >> 6, c = q & 63;
        uint32_t dst = sA + r * 1024 + (((c ^ (r & 7))) << 4);
        const __half* src = g_Ah + (size_t)(row0 + r) * DIM + c * 8;
        CP16(dst, src);
    }
    #pragma unroll
    for (int i = 0; i < 2; i++) {
        int q = t + i * NT;           // 1024 16B chunks
        uint32_t dst = sbase + SE_OFF + q * 16;
        const float* src = g_e2 + q * 4;
        CP16(dst, src);
    }
    CP_COMMIT();
    // ---- prologue B stages 0..2 ----
    #pragma unroll
    for (int s = 0; s < 3; s++) { load_B(sB, t, s, s); CP_COMMIT(); }

    float v1[4], v2[4]; int i1[4];
    #pragma unroll
    for (int s = 0; s < 4; s++) { v1[s] = FLT_MAX; v2[s] = FLT_MAX; i1[s] = 0; }

    float acc[2][4][4];

    for (int i = 0; i < 256; i++) {
        if (i <= 253)      asm volatile("cp.async.wait_group 2;" ::: "memory");
        else if (i == 254) asm volatile("cp.async.wait_group 1;" ::: "memory");
        else               asm volatile("cp.async.wait_group 0;" ::: "memory");
        __syncthreads();

        const int kk = i & 7, p = i >> 3;
        if (kk == 0) {
            #pragma unroll
            for (int mi = 0; mi < 2; mi++)
                #pragma unroll
                for (int ni = 0; ni < 4; ni++)
                    #pragma unroll
                    for (int q = 0; q < 4; q++) acc[mi][ni][q] = 0.f;
        }
        const uint32_t stg = sB + (i & 3) * 16384;

        #pragma unroll
        for (int s = 0; s < 4; s++) {
            uint32_t a[2][4];
            const int rowA = lane & 15;
            const int ca = kk * 8 + s * 2 + (lane >> 4);
            #pragma unroll
            for (int mi = 0; mi < 2; mi++) {
                int rg = wr * 32 + mi * 16 + rowA;
                uint32_t ad = sA + rg * 1024 + (((ca ^ (rg & 7))) << 4);
                LDSM4(a[mi], ad);
            }
            uint32_t b[2][4];
            const int nl = ((lane >> 4) << 3) + (lane & 7);
            const int cb = s * 2 + ((lane >> 3) & 1);
            #pragma unroll
            for (int np = 0; np < 2; np++) {
                int ng = wc * 32 + np * 16 + nl;
                uint32_t bd = stg + ng * 128 + (((cb ^ (ng & 7))) << 4);
                LDSM4(b[np], bd);
            }
            #pragma unroll
            for (int mi = 0; mi < 2; mi++)
                #pragma unroll
                for (int ni = 0; ni < 4; ni++)
                    MMA16(acc[mi][ni], a[mi], b[ni >> 1][(ni & 1) * 2],
                          b[ni >> 1][(ni & 1) * 2 + 1]);
        }

        if (kk == 7) {
            // dist = e2[col] - 2*dot ; update per-row top-2
            #pragma unroll
            for (int mi = 0; mi < 2; mi++) {
                #pragma unroll
                for (int ni = 0; ni < 4; ni++) {
                    int col = p * 128 + wc * 32 + ni * 8 + (lane & 3) * 2;
                    float ea = e2p[col], eb = e2p[col + 1];
                    float d0 = fmaf(-2.f, acc[mi][ni][0], ea);
                    float d1 = fmaf(-2.f, acc[mi][ni][1], eb);
                    float d2 = fmaf(-2.f, acc[mi][ni][2], ea);
                    float d3 = fmaf(-2.f, acc[mi][ni][3], eb);
                    int s0 = mi * 2, s1 = mi * 2 + 1;
                    if (d0 < v1[s0]) { v2[s0] = v1[s0]; v1[s0] = d0; i1[s0] = col; }
                    else if (d0 < v2[s0]) v2[s0] = d0;
                    if (d1 < v1[s0]) { v2[s0] = v1[s0]; v1[s0] = d1; i1[s0] = col + 1; }
                    else if (d1 < v2[s0]) v2[s0] = d1;
                    if (d2 < v1[s1]) { v2[s1] = v1[s1]; v1[s1] = d2; i1[s1] = col; }
                    else if (d2 < v2[s1]) v2[s1] = d2;
                    if (d3 < v1[s1]) { v2[s1] = v1[s1]; v1[s1] = d3; i1[s1] = col + 1; }
                    else if (d3 < v2[s1]) v2[s1] = d3;
                }
            }
        }
        int nx = i + 3;
        if (nx < 256) { load_B(sB, t, nx & 3, nx); CP_COMMIT(); }
    }

    // ---- intra-warp merge (4 lanes share each row) ----
    #pragma unroll
    for (int s = 0; s < 4; s++) {
        #pragma unroll
        for (int off = 1; off <= 2; off <<= 1) {
            float ov1 = __shfl_xor_sync(0xffffffffu, v1[s], off);
            int   oi1 = __shfl_xor_sync(0xffffffffu, i1[s], off);
            float ov2 = __shfl_xor_sync(0xffffffffu, v2[s], off);
            if (ov1 < v1[s] || (ov1 == v1[s] && oi1 < i1[s])) {
                v2[s] = fminf(v1[s], ov2);
                v1[s] = ov1; i1[s] = oi1;
            } else {
                v2[s] = fminf(v2[s], ov1);
            }
        }
    }
    __syncthreads();   // all compute & cp.async done; reuse B-stage SMEM
    float* mv1 = (float*)(smem + SB_OFF);
    int*   mi1 = (int*)(smem + SB_OFF + 2048);
    float* mv2 = (float*)(smem + SB_OFF + 4096);
    if ((lane & 3) == 0) {
        #pragma unroll
        for (int s = 0; s < 4; s++) {
            int m = s >> 1, h = s & 1;
            int r = wr * 32 + m * 16 + h * 8 + (lane >> 2);
            mv1[r * 4 + wc] = v1[s];
            mi1[r * 4 + wc] = i1[s];
            mv2[r * 4 + wc] = v2[s];
        }
    }
    __syncthreads();
    if (t < 128) {
        float bv = mv1[t * 4], bv2 = mv2[t * 4];
        int bi = mi1[t * 4];
        #pragma unroll
        for (int w = 1; w < 4; w++) {
            float ov1 = mv1[t * 4 + w], ov2 = mv2[t * 4 + w];
            int oi = mi1[t * 4 + w];
            if (ov1 < bv || (ov1 == bv && oi < bi)) {
                bv2 = fminf(bv, ov2); bv = ov1; bi = oi;
            } else {
                bv2 = fminf(bv2, ov1);
            }
        }
        g_best[row0 + t] = bi;
        g_margin[row0 + t] = bv2 - bv;
    }
}

// ---------------- rescue: compact + exact fp32 rescore ----------------
__global__ void compact_kernel() {
    int r = blockIdx.x * blockDim.x + threadIdx.x;
    if (r < NROWS && g_margin[r] < THRESH) {
        int p = atomicAdd(&g_cnt, 1);
        g_list[p] = r;
    }
}

// 8 rows per block share the embT stream; warp-per-code, coalesced.
__global__ __launch_bounds__(256) void rescore_kernel(const float* __restrict__ x) {
    __shared__ float xs[8][DIM];
    __shared__ float wv[8][8];
    __shared__ int   wi[8][8];
    __shared__ int   rows[8];
    const int n = g_cnt;
    const int t = threadIdx.x, w = t >> 5, lane = t & 31;

    for (int g = blockIdx.x; g * 8 < n; g += gridDim.x) {
        __syncthreads();
        if (t < 8) rows[t] = (g * 8 + t < n) ? g_list[g * 8 + t] : -1;
        __syncthreads();
        for (int idx = t; idx < 8 * DIM; idx += 256) {
            int r = idx >> 9, d = idx & 511;
            int rr = rows[r] >= 0 ? rows[r] : rows[0];
            xs[r][d] = x[(size_t)rr * DIM + d];
        }
        __syncthreads();

        float bv[8]; int bi[8];
        #pragma unroll
        for (int r = 0; r < 8; r++) { bv[r] = FLT_MAX; bi[r] = 0; }

        for (int j = w; j < NE; j += 8) {
            const float4* er = (const float4*)(g_embT + (size_t)j * DIM);
            float a[8];
            #pragma unroll
            for (int r = 0; r < 8; r++) a[r] = 0.f;
            #pragma unroll
            for (int sub = 0; sub < 4; sub++) {
                float4 e = er[sub * 32 + lane];
                #pragma unroll
                for (int r = 0; r < 8; r++) {
                    const float4 xv = *(const float4*)&xs[r][sub * 128 + lane * 4];
                    a[r] = fmaf(e.x, xv.x, a[r]);
                    a[r] = fmaf(e.y, xv.y, a[r]);
                    a[r] = fmaf(e.z, xv.z, a[r]);
                    a[r] = fmaf(e.w, xv.w, a[r]);
                }
            }
            #pragma unroll
            for (int r = 0; r < 8; r++)
                #pragma unroll
                for (int o = 16; o > 0; o >>= 1)
                    a[r] += __shfl_xor_sync(0xffffffffu, a[r], o);
            float e2 = g_e2[j];
            #pragma unroll
            for (int r = 0; r < 8; r++) {
                float d = fmaf(-2.f, a[r], e2);
                if (d < bv[r]) { bv[r] = d; bi[r] = j; }
            }
        }
        if (lane == 0) {
            #pragma unroll
            for (int r = 0; r < 8; r++) { wv[w][r] = bv[r]; wi[w][r] = bi[r]; }
        }
        __syncthreads();
        if (t < 8) {
            int r = t;
            float fb = wv[0][r]; int fi = wi[0][r];
            #pragma unroll
            for (int q = 1; q < 8; q++) {
                if (wv[q][r] < fb || (wv[q][r] == fb && wi[q][r] < fi)) {
                    fb = wv[q][r]; fi = wi[q][r];
                }
            }
            if (g * 8 + r < n) g_best[rows[r]] = fi;
        }
    }
}

// ---------------- gather + diff ----------------
__global__ __launch_bounds__(128) void gather_kernel(
    const float* __restrict__ x, float* __restrict__ out)
{
    const int row = blockIdx.x;
    const int t = threadIdx.x;
    const int idx = g_best[row];
    const float4* q4 = (const float4*)(g_embT + (size_t)idx * DIM);
    const float4* x4 = (const float4*)(x + (size_t)row * DIM);
    float4* o4 = (float4*)(out + (size_t)row * DIM);

    float4 q = q4[t];
    float4 xv = x4[t];
    float dx = q.x - xv.x, dy = q.y - xv.y, dz = q.z - xv.z, dw = q.w - xv.w;
    float4 o;
    o.x = xv.x + dx; o.y = xv.y + dy; o.z = xv.z + dz; o.w = xv.w + dw;
    o4[t] = o;
    float s = dx * dx + dy * dy + dz * dz + dw * dw;

    __shared__ float red[128];
    red[t] = s;
    __syncthreads();
    #pragma unroll
    for (int off = 64; off > 0; off >>= 1) {
        if (t < off) red[t] += red[t + off];
        __syncthreads();
    }
    if (t == 0) {
        g_partial[row] = red[0];
        out[(size_t)NROWS * DIM + 1 + row] = (float)idx;
    }
}

__global__ void final_kernel(float* __restrict__ out) {
    __shared__ double red[256];
    int t = threadIdx.x;
    double s = 0.0;
    for (int i = t; i < NROWS; i += 256) s += (double)g_partial[i];
    red[t] = s;
    __syncthreads();
    for (int off = 128; off > 0; off >>= 1) {
        if (t < off) red[t] += red[t + off];
        __syncthreads();
    }
    if (t == 0)
        out[(size_t)NROWS * DIM] = (float)(red[0] / ((double)NROWS * (double)DIM));
}

// ----------------------------------------------------------------
extern "C" void kernel_launch(void* const* d_in, const int* in_sizes, int n_in,
                              void* d_out, int out_size) {
    const float* x     = (const float*)d_in[0];
    const float* embed = (const float*)d_in[1];
    float* out = (float*)d_out;

    cudaFuncSetAttribute(gemm_argmin_kernel,
                         cudaFuncAttributeMaxDynamicSharedMemorySize, SMEM_SZ);

    pack_x_kernel<<<NROWS * DIM / 4 / 256, 256>>>(x);
    pack_embed_kernel<<<dim3(NE / 32, DIM / 32), dim3(32, 8)>>>(embed);
    prep_e2<<<NE / 256, 256>>>(embed);
    gemm_argmin_kernel<<<NROWS / 128, NT, SMEM_SZ>>>();
    compact_kernel<<<NROWS / 256, 256>>>();
    rescore_kernel<<<256, 256>>>(x);
    gather_kernel<<<NROWS, 128>>>(x, out);
    final_kernel<<<1, 256>>>(out);
}

// round 12
// speedup vs baseline: 1.2875x; 1.2875x over previous
#include <cuda_runtime.h>
#include <cuda_fp16.h>
#include <cstdint>
#include <cfloat>

#define DIM    512
#define NE     4096
#define NROWS  65536
#define THRESH 0.35f

// ---------------- scratch (__device__ globals) ----------------
__device__ __align__(128) __half g_Ah[(size_t)NROWS * DIM];  // x as fp16
__device__ __align__(128) __half g_Bh[(size_t)NE * DIM];     // embT as fp16
__device__ float g_embT[(size_t)NE * DIM];
__device__ float g_e2[NE];
__device__ int   g_best[NROWS];
__device__ float g_partial[NROWS];
__device__ int   g_list[NROWS];       // fallback rows (full rescore)
__device__ int   g_cnt;
__device__ int2  g_pairs[(size_t)NROWS * 16];  // (row, code) exact-check pairs
__device__ int   g_pcnt;
__device__ unsigned long long g_pack[NROWS];   // atomicMin (dist|idx)

// ---------------- asm helpers ----------------
__device__ __forceinline__ uint32_t smem_u32(const void* p) {
    uint32_t a;
    asm("{ .reg .u64 t; cvta.to.shared.u64 t, %1; cvt.u32.u64 %0, t; }" : "=r"(a) : "l"(p));
    return a;
}
#define CP16(dst, src) \
    asm volatile("cp.async.cg.shared.global [%0], [%1], 16;" :: "r"(dst), "l"(src))
#define CP_COMMIT() asm volatile("cp.async.commit_group;" ::: "memory")

#define LDSM4(r, addr) \
    asm volatile("ldmatrix.sync.aligned.m8n8.x4.shared.b16 {%0,%1,%2,%3}, [%4];" \
        : "=r"((r)[0]), "=r"((r)[1]), "=r"((r)[2]), "=r"((r)[3]) : "r"(addr))

#define MMA16(c, a, b0, b1) \
    asm volatile("mma.sync.aligned.m16n8k16.row.col.f32.f16.f16.f32 " \
        "{%0,%1,%2,%3},{%4,%5,%6,%7},{%8,%9},{%0,%1,%2,%3};" \
        : "+f"((c)[0]), "+f"((c)[1]), "+f"((c)[2]), "+f"((c)[3]) \
        : "r"((a)[0]), "r"((a)[1]), "r"((a)[2]), "r"((a)[3]), "r"(b0), "r"(b1))

// ---------------- prep: pack x -> fp16 ----------------
__global__ __launch_bounds__(256) void pack_x_kernel(const float* __restrict__ x) {
    size_t g = (size_t)blockIdx.x * 256 + threadIdx.x;
    if (g == 0) { g_cnt = 0; g_pcnt = 0; }
    size_t e = g * 4;
    float4 v = *(const float4*)(x + e);
    __half2 h0 = __floats2half2_rn(v.x, v.y);
    __half2 h1 = __floats2half2_rn(v.z, v.w);
    uint2 pk;
    pk.x = *(uint32_t*)&h0;
    pk.y = *(uint32_t*)&h1;
    *(uint2*)(g_Ah + e) = pk;
}

// ---------------- prep: transpose embed -> fp16 B + fp32 embT ----------------
__global__ void pack_embed_kernel(const float* __restrict__ embed) {
    __shared__ float tile[32][33];
    int jb = blockIdx.x * 32;
    int db = blockIdx.y * 32;
    int tx = threadIdx.x, ty = threadIdx.y;  // 32 x 8
    #pragma unroll
    for (int d = ty; d < 32; d += 8)
        tile[d][tx] = embed[(size_t)(db + d) * NE + jb + tx];
    __syncthreads();
    #pragma unroll
    for (int j = ty; j < 32; j += 8) {
        float v = tile[tx][j];
        size_t o = (size_t)(jb + j) * DIM + db + tx;
        g_Bh[o]   = __float2half_rn(v);
        g_embT[o] = v;
    }
}

__global__ void prep_e2(const float* __restrict__ embed) {
    int j = blockIdx.x * blockDim.x + threadIdx.x;
    if (j < NE) {
        float s = 0.f;
        #pragma unroll 8
        for (int d = 0; d < DIM; d++) {
            float v = embed[(size_t)d * NE + j];
            s = fmaf(v, v, s);
        }
        g_e2[j] = s;
    }
}

// ---------------- GEMM + argmin (mma.sync fp16, 512 threads) --------
// SMEM layout (dynamic, 212992 B):
//   [0, 131072)        A block 128 x 512 fp16, swizzled
//   [131072, 196608)   B stages: 4 x 16384 (reused post-loop: MV1/MI1/MV2)
//   [196608, 212992)   e2[4096] fp32
#define SA_OFF 0
#define SB_OFF 131072
#define SE_OFF 196608
#define SMEM_SZ 212992
#define NT 512

__device__ __forceinline__ void load_B(uint32_t sB, int t, int slot, int idx) {
    const int col0 = (idx >> 3) << 7;
    const int kk = idx & 7;
    const __half* base = g_Bh + (size_t)col0 * DIM + kk * 64;
    uint32_t sbase = sB + slot * 16384;
    #pragma unroll
    for (int i = 0; i < 2; i++) {
        int q = t + i * NT;
        int n = q >> 3, ck = q & 7;
        uint32_t dst = sbase + n * 128 + (((ck ^ (n & 7))) << 4);
        const __half* src = base + (size_t)n * DIM + ck * 8;
        CP16(dst, src);
    }
}

__global__ __launch_bounds__(NT, 1) void gemm_argmin_kernel() {
    extern __shared__ __align__(128) char smem[];
    const uint32_t sbase = smem_u32(smem);
    const uint32_t sA = sbase + SA_OFF;
    const uint32_t sB = sbase + SB_OFF;
    const int t = threadIdx.x;
    const int lane = t & 31, warp = t >> 5;
    const int wr = warp >> 2, wc = warp & 3;      // 4 x 4 warp grid
    const int row0 = blockIdx.x * 128;
    float* e2p = (float*)(smem + SE_OFF);

    // ---- group 0: A block (128x512 fp16) + e2 ----
    #pragma unroll
    for (int i = 0; i < 16; i++) {
        int q = t + i * NT;           // 8192 16B chunks
        int r = q >> 6, c = q & 63;
        uint32_t dst = sA + r * 1024 + (((c ^ (r & 7))) << 4);
        const __half* src = g_Ah + (size_t)(row0 + r) * DIM + c * 8;
        CP16(dst, src);
    }
    #pragma unroll
    for (int i = 0; i < 2; i++) {
        int q = t + i * NT;           // 1024 16B chunks
        uint32_t dst = sbase + SE_OFF + q * 16;
        const float* src = g_e2 + q * 4;
        CP16(dst, src);
    }
    CP_COMMIT();
    // ---- prologue B stages 0..2 ----
    #pragma unroll
    for (int s = 0; s < 3; s++) { load_B(sB, t, s, s); CP_COMMIT(); }

    float v1[4], v2[4]; int i1[4];
    #pragma unroll
    for (int s = 0; s < 4; s++) { v1[s] = FLT_MAX; v2[s] = FLT_MAX; i1[s] = 0; }

    float acc[2][4][4];

    for (int i = 0; i < 256; i++) {
        if (i <= 253)      asm volatile("cp.async.wait_group 2;" ::: "memory");
        else if (i == 254) asm volatile("cp.async.wait_group 1;" ::: "memory");
        else               asm volatile("cp.async.wait_group 0;" ::: "memory");
        __syncthreads();

        const int kk = i & 7, p = i >> 3;
        if (kk == 0) {
            #pragma unroll
            for (int mi = 0; mi < 2; mi++)
                #pragma unroll
                for (int ni = 0; ni < 4; ni++)
                    #pragma unroll
                    for (int q = 0; q < 4; q++) acc[mi][ni][q] = 0.f;
        }
        const uint32_t stg = sB + (i & 3) * 16384;

        #pragma unroll
        for (int s = 0; s < 4; s++) {
            uint32_t a[2][4];
            const int rowA = lane & 15;
            const int ca = kk * 8 + s * 2 + (lane >> 4);
            #pragma unroll
            for (int mi = 0; mi < 2; mi++) {
                int rg = wr * 32 + mi * 16 + rowA;
                uint32_t ad = sA + rg * 1024 + (((ca ^ (rg & 7))) << 4);
                LDSM4(a[mi], ad);
            }
            uint32_t b[2][4];
            const int nl = ((lane >> 4) << 3) + (lane & 7);
            const int cb = s * 2 + ((lane >> 3) & 1);
            #pragma unroll
            for (int np = 0; np < 2; np++) {
                int ng = wc * 32 + np * 16 + nl;
                uint32_t bd = stg + ng * 128 + (((cb ^ (ng & 7))) << 4);
                LDSM4(b[np], bd);
            }
            #pragma unroll
            for (int mi = 0; mi < 2; mi++)
                #pragma unroll
                for (int ni = 0; ni < 4; ni++)
                    MMA16(acc[mi][ni], a[mi], b[ni >> 1][(ni & 1) * 2],
                          b[ni >> 1][(ni & 1) * 2 + 1]);
        }

        if (kk == 7) {
            // dist = e2[col] - 2*dot ; update per-slot top-2
            #pragma unroll
            for (int mi = 0; mi < 2; mi++) {
                #pragma unroll
                for (int ni = 0; ni < 4; ni++) {
                    int col = p * 128 + wc * 32 + ni * 8 + (lane & 3) * 2;
                    float ea = e2p[col], eb = e2p[col + 1];
                    float d0 = fmaf(-2.f, acc[mi][ni][0], ea);
                    float d1 = fmaf(-2.f, acc[mi][ni][1], eb);
                    float d2 = fmaf(-2.f, acc[mi][ni][2], ea);
                    float d3 = fmaf(-2.f, acc[mi][ni][3], eb);
                    int s0 = mi * 2, s1 = mi * 2 + 1;
                    if (d0 < v1[s0]) { v2[s0] = v1[s0]; v1[s0] = d0; i1[s0] = col; }
                    else if (d0 < v2[s0]) v2[s0] = d0;
                    if (d1 < v1[s0]) { v2[s0] = v1[s0]; v1[s0] = d1; i1[s0] = col + 1; }
                    else if (d1 < v2[s0]) v2[s0] = d1;
                    if (d2 < v1[s1]) { v2[s1] = v1[s1]; v1[s1] = d2; i1[s1] = col; }
                    else if (d2 < v2[s1]) v2[s1] = d2;
                    if (d3 < v1[s1]) { v2[s1] = v1[s1]; v1[s1] = d3; i1[s1] = col + 1; }
                    else if (d3 < v2[s1]) v2[s1] = d3;
                }
            }
        }
        int nx = i + 3;
        if (nx < 256) { load_B(sB, t, nx & 3, nx); CP_COMMIT(); }
    }

    // ---- store 16 per-row partials (no lane merge; each covers 256 cols) ----
    __syncthreads();   // all compute & cp.async done; reuse B-stage SMEM
    float* MV1 = (float*)(smem + SB_OFF);
    int*   MI1 = (int*)  (smem + SB_OFF + 8704);
    float* MV2 = (float*)(smem + SB_OFF + 17408);
    {
        const int pi = wc * 4 + (lane & 3);
        #pragma unroll
        for (int s = 0; s < 4; s++) {
            int mi = s >> 1, h = s & 1;
            int r = wr * 32 + mi * 16 + h * 8 + (lane >> 2);
            int o = r * 17 + pi;
            MV1[o] = v1[s]; MI1[o] = i1[s]; MV2[o] = v2[s];
        }
    }
    __syncthreads();
    if (t < 128) {
        const int base = t * 17;
        // global best with first-occurrence tie-break
        float d1 = FLT_MAX; int bi = 0x7fffffff;
        #pragma unroll
        for (int p = 0; p < 16; p++) {
            float v = MV1[base + p]; int id = MI1[base + p];
            if (v < d1 || (v == d1 && id < bi)) { d1 = v; bi = id; }
        }
        // global second (value only)
        float d2 = FLT_MAX;
        #pragma unroll
        for (int p = 0; p < 16; p++) {
            float v = (MI1[base + p] == bi) ? MV2[base + p] : MV1[base + p];
            if (v < d2) d2 = v;
        }
        g_best[row0 + t] = bi;
        if (d2 - d1 < THRESH) {
            float lim = d1 + THRESH;
            bool fb = false;
            #pragma unroll
            for (int p = 0; p < 16; p++)
                if (MV2[base + p] <= lim) fb = true;
            if (fb) {
                int q = atomicAdd(&g_cnt, 1);
                g_list[q] = row0 + t;
            } else {
                g_pack[row0 + t] = 0xFFFFFFFFFFFFFFFFULL;
                #pragma unroll
                for (int p = 0; p < 16; p++) {
                    if (MV1[base + p] <= lim) {
                        int q = atomicAdd(&g_pcnt, 1);
                        g_pairs[q] = make_int2(row0 + t, MI1[base + p]);
                    }
                }
            }
        }
    }
}

// ---------------- exact fp32 check of candidate (row, code) pairs ----------
__global__ __launch_bounds__(256) void cand_kernel(const float* __restrict__ x) {
    const int np = g_pcnt;
    const int lane = threadIdx.x & 31;
    for (int i = blockIdx.x * 8 + (threadIdx.x >> 5); i < np; i += gridDim.x * 8) {
        int2 pr = g_pairs[i];
        const float4* xr = (const float4*)(x + (size_t)pr.x * DIM);
        const float4* er = (const float4*)(g_embT + (size_t)pr.y * DIM);
        float s = 0.f;
        #pragma unroll
        for (int c = 0; c < 4; c++) {
            float4 a = xr[c * 32 + lane];
            float4 b = er[c * 32 + lane];
            s = fmaf(a.x, b.x, s); s = fmaf(a.y, b.y, s);
            s = fmaf(a.z, b.z, s); s = fmaf(a.w, b.w, s);
        }
        #pragma unroll
        for (int o = 16; o > 0; o >>= 1) s += __shfl_xor_sync(0xffffffffu, s, o);
        if (lane == 0) {
            float dist = fmaf(-2.f, s, g_e2[pr.y]);
            uint32_t b = __float_as_uint(dist);
            b = (b >> 31) ? ~b : (b | 0x80000000u);   // order-preserving map
            unsigned long long pk = ((unsigned long long)b << 32) | (uint32_t)pr.y;
            atomicMin(&g_pack[pr.x], pk);
        }
    }
}

__global__ void fixup_kernel() {
    const int np = g_pcnt;
    for (int i = blockIdx.x * blockDim.x + threadIdx.x; i < np;
         i += gridDim.x * blockDim.x) {
        int row = g_pairs[i].x;
        g_best[row] = (int)(g_pack[row] & 0xFFFFFFFFULL);
    }
}

// ---------------- fallback: full fp32 rescore (rare flat rows) -------------
__global__ __launch_bounds__(256) void rescore_kernel(const float* __restrict__ x) {
    __shared__ float xs[8][DIM];
    __shared__ float wv[8][8];
    __shared__ int   wi[8][8];
    __shared__ int   rows[8];
    const int n = g_cnt;
    const int t = threadIdx.x, w = t >> 5, lane = t & 31;

    for (int g = blockIdx.x; g * 8 < n; g += gridDim.x) {
        __syncthreads();
        if (t < 8) rows[t] = (g * 8 + t < n) ? g_list[g * 8 + t] : -1;
        __syncthreads();
        for (int idx = t; idx < 8 * DIM; idx += 256) {
            int r = idx >> 9, d = idx & 511;
            int rr = rows[r] >= 0 ? rows[r] : rows[0];
            xs[r][d] = x[(size_t)rr * DIM + d];
        }
        __syncthreads();

        float bv[8]; int bi[8];
        #pragma unroll
        for (int r = 0; r < 8; r++) { bv[r] = FLT_MAX; bi[r] = 0; }

        for (int j = w; j < NE; j += 8) {
            const float4* er = (const float4*)(g_embT + (size_t)j * DIM);
            float a[8];
            #pragma unroll
            for (int r = 0; r < 8; r++) a[r] = 0.f;
            #pragma unroll
            for (int sub = 0; sub < 4; sub++) {
                float4 e = er[sub * 32 + lane];
                #pragma unroll
                for (int r = 0; r < 8; r++) {
                    const float4 xv = *(const float4*)&xs[r][sub * 128 + lane * 4];
                    a[r] = fmaf(e.x, xv.x, a[r]);
                    a[r] = fmaf(e.y, xv.y, a[r]);
                    a[r] = fmaf(e.z, xv.z, a[r]);
                    a[r] = fmaf(e.w, xv.w, a[r]);
                }
            }
            #pragma unroll
            for (int r = 0; r < 8; r++)
                #pragma unroll
                for (int o = 16; o > 0; o >>= 1)
                    a[r] += __shfl_xor_sync(0xffffffffu, a[r], o);
            float e2 = g_e2[j];
            #pragma unroll
            for (int r = 0; r < 8; r++) {
                float d = fmaf(-2.f, a[r], e2);
                if (d < bv[r]) { bv[r] = d; bi[r] = j; }
            }
        }
        if (lane == 0) {
            #pragma unroll
            for (int r = 0; r < 8; r++) { wv[w][r] = bv[r]; wi[w][r] = bi[r]; }
        }
        __syncthreads();
        if (t < 8) {
            int r = t;
            float fb = wv[0][r]; int fi = wi[0][r];
            #pragma unroll
            for (int q = 1; q < 8; q++) {
                if (wv[q][r] < fb || (wv[q][r] == fb && wi[q][r] < fi)) {
                    fb = wv[q][r]; fi = wi[q][r];
                }
            }
            if (g * 8 + r < n) g_best[rows[r]] = fi;
        }
    }
}

// ---------------- gather + diff ----------------
__global__ __launch_bounds__(128) void gather_kernel(
    const float* __restrict__ x, float* __restrict__ out)
{
    const int row = blockIdx.x;
    const int t = threadIdx.x;
    const int idx = g_best[row];
    const float4* q4 = (const float4*)(g_embT + (size_t)idx * DIM);
    const float4* x4 = (const float4*)(x + (size_t)row * DIM);
    float4* o4 = (float4*)(out + (size_t)row * DIM);

    float4 q = q4[t];
    float4 xv = x4[t];
    float dx = q.x - xv.x, dy = q.y - xv.y, dz = q.z - xv.z, dw = q.w - xv.w;
    float4 o;
    o.x = xv.x + dx; o.y = xv.y + dy; o.z = xv.z + dz; o.w = xv.w + dw;
    o4[t] = o;
    float s = dx * dx + dy * dy + dz * dz + dw * dw;

    __shared__ float red[128];
    red[t] = s;
    __syncthreads();
    #pragma unroll
    for (int off = 64; off > 0; off >>= 1) {
        if (t < off) red[t] += red[t + off];
        __syncthreads();
    }
    if (t == 0) {
        g_partial[row] = red[0];
        out[(size_t)NROWS * DIM + 1 + row] = (float)idx;
    }
}

__global__ void final_kernel(float* __restrict__ out) {
    __shared__ double red[256];
    int t = threadIdx.x;
    double s = 0.0;
    for (int i = t; i < NROWS; i += 256) s += (double)g_partial[i];
    red[t] = s;
    __syncthreads();
    for (int off = 128; off > 0; off >>= 1) {
        if (t < off) red[t] += red[t + off];
        __syncthreads();
    }
    if (t == 0)
        out[(size_t)NROWS * DIM] = (float)(red[0] / ((double)NROWS * (double)DIM));
}

// ----------------------------------------------------------------
extern "C" void kernel_launch(void* const* d_in, const int* in_sizes, int n_in,
                              void* d_out, int out_size) {
    const float* x     = (const float*)d_in[0];
    const float* embed = (const float*)d_in[1];
    float* out = (float*)d_out;

    cudaFuncSetAttribute(gemm_argmin_kernel,
                         cudaFuncAttributeMaxDynamicSharedMemorySize, SMEM_SZ);

    pack_x_kernel<<<NROWS * DIM / 4 / 256, 256>>>(x);
    pack_embed_kernel<<<dim3(NE / 32, DIM / 32), dim3(32, 8)>>>(embed);
    prep_e2<<<NE / 256, 256>>>(embed);
    gemm_argmin_kernel<<<NROWS / 128, NT, SMEM_SZ>>>();
    cand_kernel<<<1024, 256>>>(x);
    fixup_kernel<<<256, 256>>>();
    rescore_kernel<<<256, 256>>>(x);
    gather_kernel<<<NROWS, 128>>>(x, out);
    final_kernel<<<1, 256>>>(out);
}

// round 15
// speedup vs baseline: 1.3107x; 1.0180x over previous
#include <cuda_runtime.h>
#include <cuda_fp16.h>
#include <cstdint>
#include <cfloat>

#define DIM    512
#define NE     4096
#define NROWS  65536
#define THRESH 0.15f

// ---------------- scratch (__device__ globals) ----------------
__device__ __align__(128) __half g_Ah[(size_t)NROWS * DIM];  // x as fp16
__device__ __align__(128) __half g_Bh[(size_t)NE * DIM];     // embT as fp16
__device__ float g_embT[(size_t)NE * DIM];
__device__ float g_e2[NE];
__device__ int   g_best[NROWS];
__device__ float g_partial[NROWS];
__device__ int   g_list[NROWS];       // fallback rows (full rescore)
__device__ int   g_cnt;
__device__ int2  g_pairs[(size_t)NROWS * 16];  // (row, code) exact-check pairs
__device__ int   g_pcnt;
__device__ unsigned long long g_pack[NROWS];   // atomicMin (dist|idx)

// ---------------- asm helpers ----------------
__device__ __forceinline__ uint32_t smem_u32(const void* p) {
    uint32_t a;
    asm("{ .reg .u64 t; cvta.to.shared.u64 t, %1; cvt.u32.u64 %0, t; }" : "=r"(a) : "l"(p));
    return a;
}
#define CP16(dst, src) \
    asm volatile("cp.async.cg.shared.global [%0], [%1], 16;" :: "r"(dst), "l"(src))
#define CP_COMMIT() asm volatile("cp.async.commit_group;" ::: "memory")

#define LDSM4(r, addr) \
    asm volatile("ldmatrix.sync.aligned.m8n8.x4.shared.b16 {%0,%1,%2,%3}, [%4];" \
        : "=r"((r)[0]), "=r"((r)[1]), "=r"((r)[2]), "=r"((r)[3]) : "r"(addr))

#define MMA16(c, a, b0, b1) \
    asm volatile("mma.sync.aligned.m16n8k16.row.col.f32.f16.f16.f32 " \
        "{%0,%1,%2,%3},{%4,%5,%6,%7},{%8,%9},{%0,%1,%2,%3};" \
        : "+f"((c)[0]), "+f"((c)[1]), "+f"((c)[2]), "+f"((c)[3]) \
        : "r"((a)[0]), "r"((a)[1]), "r"((a)[2]), "r"((a)[3]), "r"(b0), "r"(b1))

// ---------------- prep: pack x -> fp16 ----------------
__global__ __launch_bounds__(256) void pack_x_kernel(const float* __restrict__ x) {
    size_t g = (size_t)blockIdx.x * 256 + threadIdx.x;
    if (g == 0) { g_cnt = 0; g_pcnt = 0; }
    size_t e = g * 4;
    float4 v = *(const float4*)(x + e);
    __half2 h0 = __floats2half2_rn(v.x, v.y);
    __half2 h1 = __floats2half2_rn(v.z, v.w);
    uint2 pk;
    pk.x = *(uint32_t*)&h0;
    pk.y = *(uint32_t*)&h1;
    *(uint2*)(g_Ah + e) = pk;
}

// ---------------- prep: transpose embed -> fp16 B + fp32 embT ----------------
__global__ void pack_embed_kernel(const float* __restrict__ embed) {
    __shared__ float tile[32][33];
    int jb = blockIdx.x * 32;
    int db = blockIdx.y * 32;
    int tx = threadIdx.x, ty = threadIdx.y;  // 32 x 8
    #pragma unroll
    for (int d = ty; d < 32; d += 8)
        tile[d][tx] = embed[(size_t)(db + d) * NE + jb + tx];
    __syncthreads();
    #pragma unroll
    for (int j = ty; j < 32; j += 8) {
        float v = tile[tx][j];
        size_t o = (size_t)(jb + j) * DIM + db + tx;
        g_Bh[o]   = __float2half_rn(v);
        g_embT[o] = v;
    }
}

__global__ void prep_e2(const float* __restrict__ embed) {
    int j = blockIdx.x * blockDim.x + threadIdx.x;
    if (j < NE) {
        float s = 0.f;
        #pragma unroll 8
        for (int d = 0; d < DIM; d++) {
            float v = embed[(size_t)d * NE + j];
            s = fmaf(v, v, s);
        }
        g_e2[j] = s;
    }
}

// ---------------- GEMM + argmin (mma.sync fp16, 512 threads) --------
// SMEM layout (dynamic, 229376 B):
//   [0, 131072)        A block 128 x 512 fp16, swizzled
//   [131072, 229376)   B stages: 6 x 16384 (128n x 64k fp16, swizzled)
//                      (reused post-loop as merge buffer MV1/MI1/MV2)
//   e2 read via __ldg in epilogue (L2-resident)
#define SA_OFF 0
#define SB_OFF 131072
#define SMEM_SZ 229376
#define NT 512

__device__ __forceinline__ void load_B(uint32_t sB, int t, int slot, int idx) {
    const int col0 = (idx >> 3) << 7;
    const int kk = idx & 7;
    const __half* base = g_Bh + (size_t)col0 * DIM + kk * 64;
    uint32_t sbase = sB + slot * 16384;
    #pragma unroll
    for (int i = 0; i < 2; i++) {
        int q = t + i * NT;
        int n = q >> 3, ck = q & 7;
        uint32_t dst = sbase + n * 128 + (((ck ^ (n & 7))) << 4);
        const __half* src = base + (size_t)n * DIM + ck * 8;
        CP16(dst, src);
    }
}

__global__ __launch_bounds__(NT, 1) void gemm_argmin_kernel() {
    extern __shared__ __align__(128) char smem[];
    const uint32_t sbase = smem_u32(smem);
    const uint32_t sA = sbase + SA_OFF;
    const uint32_t sB = sbase + SB_OFF;
    const int t = threadIdx.x;
    const int lane = t & 31, warp = t >> 5;
    const int wr = warp >> 2, wc = warp & 3;      // 4 x 4 warp grid
    const int row0 = blockIdx.x * 128;

    // ---- group 0: A block (128x512 fp16) ----
    #pragma unroll
    for (int i = 0; i < 16; i++) {
        int q = t + i * NT;           // 8192 16B chunks
        int r = q >> 6, c = q & 63;
        uint32_t dst = sA + r * 1024 + (((c ^ (r & 7))) << 4);
        const __half* src = g_Ah + (size_t)(row0 + r) * DIM + c * 8;
        CP16(dst, src);
    }
    CP_COMMIT();
    // ---- prologue B stages 0..3 (slots 0..3 of 6) ----
    #pragma unroll
    for (int s = 0; s < 4; s++) { load_B(sB, t, s, s); CP_COMMIT(); }

    float v1[4], v2[4]; int i1[4];
    #pragma unroll
    for (int s = 0; s < 4; s++) { v1[s] = FLT_MAX; v2[s] = FLT_MAX; i1[s] = 0; }

    float acc[2][4][4];

    // 128 iterations; each consumes TWO 64k stages between syncs.
    for (int j = 0; j < 128; j++) {
        if (j < 127) asm volatile("cp.async.wait_group 2;" ::: "memory");
        else         asm volatile("cp.async.wait_group 0;" ::: "memory");
        __syncthreads();

        if ((j & 3) == 0) {
            #pragma unroll
            for (int mi = 0; mi < 2; mi++)
                #pragma unroll
                for (int ni = 0; ni < 4; ni++)
                    #pragma unroll
                    for (int q = 0; q < 4; q++) acc[mi][ni][q] = 0.f;
        }

        #pragma unroll
        for (int half = 0; half < 2; half++) {
            const int st = 2 * j + half;
            const uint32_t stg = sB + (st % 6) * 16384;
            const int kk = st & 7;

            #pragma unroll
            for (int s = 0; s < 4; s++) {
                uint32_t a[2][4];
                const int rowA = lane & 15;
                const int ca = kk * 8 + s * 2 + (lane >> 4);
                #pragma unroll
                for (int mi = 0; mi < 2; mi++) {
                    int rg = wr * 32 + mi * 16 + rowA;
                    uint32_t ad = sA + rg * 1024 + (((ca ^ (rg & 7))) << 4);
                    LDSM4(a[mi], ad);
                }
                uint32_t b[2][4];
                const int nl = ((lane >> 4) << 3) + (lane & 7);
                const int cb = s * 2 + ((lane >> 3) & 1);
                #pragma unroll
                for (int np = 0; np < 2; np++) {
                    int ng = wc * 32 + np * 16 + nl;
                    uint32_t bd = stg + ng * 128 + (((cb ^ (ng & 7))) << 4);
                    LDSM4(b[np], bd);
                }
                #pragma unroll
                for (int mi = 0; mi < 2; mi++)
                    #pragma unroll
                    for (int ni = 0; ni < 4; ni++)
                        MMA16(acc[mi][ni], a[mi], b[ni >> 1][(ni & 1) * 2],
                              b[ni >> 1][(ni & 1) * 2 + 1]);
            }
        }

        if ((j & 3) == 3) {
            // end of pass p: dist = e2[col] - 2*dot ; per-slot top-2
            const int p = j >> 2;
            #pragma unroll
            for (int mi = 0; mi < 2; mi++) {
                #pragma unroll
                for (int ni = 0; ni < 4; ni++) {
                    int col = p * 128 + wc * 32 + ni * 8 + (lane & 3) * 2;
                    float ea = __ldg(&g_e2[col]), eb = __ldg(&g_e2[col + 1]);
                    float d0 = fmaf(-2.f, acc[mi][ni][0], ea);
                    float d1 = fmaf(-2.f, acc[mi][ni][1], eb);
                    float d2 = fmaf(-2.f, acc[mi][ni][2], ea);
                    float d3 = fmaf(-2.f, acc[mi][ni][3], eb);
                    int s0 = mi * 2, s1 = mi * 2 + 1;
                    if (d0 < v1[s0]) { v2[s0] = v1[s0]; v1[s0] = d0; i1[s0] = col; }
                    else if (d0 < v2[s0]) v2[s0] = d0;
                    if (d1 < v1[s0]) { v2[s0] = v1[s0]; v1[s0] = d1; i1[s0] = col + 1; }
                    else if (d1 < v2[s0]) v2[s0] = d1;
                    if (d2 < v1[s1]) { v2[s1] = v1[s1]; v1[s1] = d2; i1[s1] = col; }
                    else if (d2 < v2[s1]) v2[s1] = d2;
                    if (d3 < v1[s1]) { v2[s1] = v1[s1]; v1[s1] = d3; i1[s1] = col + 1; }
                    else if (d3 < v2[s1]) v2[s1] = d3;
                }
            }
        }
        // refill stages 2j+4, 2j+5 into slots consumed at iter j-1
        if (j < 126) {
            int sa = 2 * j + 4, sb = 2 * j + 5;
            load_B(sB, t, sa % 6, sa); CP_COMMIT();
            load_B(sB, t, sb % 6, sb); CP_COMMIT();
        }
    }

    // ---- store 16 per-row partials (no lane merge; each covers 256 cols) ----
    __syncthreads();   // all compute & cp.async done; reuse B-stage SMEM
    float* MV1 = (float*)(smem + SB_OFF);
    int*   MI1 = (int*)  (smem + SB_OFF + 8704);
    float* MV2 = (float*)(smem + SB_OFF + 17408);
    {
        const int pi = wc * 4 + (lane & 3);
        #pragma unroll
        for (int s = 0; s < 4; s++) {
            int mi = s >> 1, h = s & 1;
            int r = wr * 32 + mi * 16 + h * 8 + (lane >> 2);
            int o = r * 17 + pi;
            MV1[o] = v1[s]; MI1[o] = i1[s]; MV2[o] = v2[s];
        }
    }
    __syncthreads();
    if (t < 128) {
        const int base = t * 17;
        float d1 = FLT_MAX; int bi = 0x7fffffff;
        #pragma unroll
        for (int p = 0; p < 16; p++) {
            float v = MV1[base + p]; int id = MI1[base + p];
            if (v < d1 || (v == d1 && id < bi)) { d1 = v; bi = id; }
        }
        float d2 = FLT_MAX;
        #pragma unroll
        for (int p = 0; p < 16; p++) {
            float v = (MI1[base + p] == bi) ? MV2[base + p] : MV1[base + p];
            if (v < d2) d2 = v;
        }
        g_best[row0 + t] = bi;
        if (d2 - d1 < THRESH) {
            float lim = d1 + THRESH;
            bool fb = false;
            #pragma unroll
            for (int p = 0; p < 16; p++)
                if (MV2[base + p] <= lim) fb = true;
            if (fb) {
                int q = atomicAdd(&g_cnt, 1);
                g_list[q] = row0 + t;
            } else {
                g_pack[row0 + t] = 0xFFFFFFFFFFFFFFFFULL;
                #pragma unroll
                for (int p = 0; p < 16; p++) {
                    if (MV1[base + p] <= lim) {
                        int q = atomicAdd(&g_pcnt, 1);
                        g_pairs[q] = make_int2(row0 + t, MI1[base + p]);
                    }
                }
            }
        }
    }
}

// ---------------- exact fp32 check of candidate (row, code) pairs ----------
__global__ __launch_bounds__(256) void cand_kernel(const float* __restrict__ x) {
    const int np = g_pcnt;
    const int lane = threadIdx.x & 31;
    for (int i = blockIdx.x * 8 + (threadIdx.x >> 5); i < np; i += gridDim.x * 8) {
        int2 pr = g_pairs[i];
        const float4* xr = (const float4*)(x + (size_t)pr.x * DIM);
        const float4* er = (const float4*)(g_embT + (size_t)pr.y * DIM);
        float s = 0.f;
        #pragma unroll
        for (int c = 0; c < 4; c++) {
            float4 a = xr[c * 32 + lane];
            float4 b = er[c * 32 + lane];
            s = fmaf(a.x, b.x, s); s = fmaf(a.y, b.y, s);
            s = fmaf(a.z, b.z, s); s = fmaf(a.w, b.w, s);
        }
        #pragma unroll
        for (int o = 16; o > 0; o >>= 1) s += __shfl_xor_sync(0xffffffffu, s, o);
        if (lane == 0) {
            float dist = fmaf(-2.f, s, g_e2[pr.y]);
            uint32_t b = __float_as_uint(dist);
            b = (b >> 31) ? ~b : (b | 0x80000000u);   // order-preserving map
            unsigned long long pk = ((unsigned long long)b << 32) | (uint32_t)pr.y;
            atomicMin(&g_pack[pr.x], pk);
        }
    }
}

__global__ void fixup_kernel() {
    const int np = g_pcnt;
    for (int i = blockIdx.x * blockDim.x + threadIdx.x; i < np;
         i += gridDim.x * blockDim.x) {
        int row = g_pairs[i].x;
        g_best[row] = (int)(g_pack[row] & 0xFFFFFFFFULL);
    }
}

// ---------------- fallback: full fp32 rescore (rare flat rows) -------------
__global__ __launch_bounds__(256) void rescore_kernel(const float* __restrict__ x) {
    __shared__ float xs[8][DIM];
    __shared__ float wv[8][8];
    __shared__ int   wi[8][8];
    __shared__ int   rows[8];
    const int n = g_cnt;
    const int t = threadIdx.x, w = t >> 5, lane = t & 31;

    for (int g = blockIdx.x; g * 8 < n; g += gridDim.x) {
        __syncthreads();
        if (t < 8) rows[t] = (g * 8 + t < n) ? g_list[g * 8 + t] : -1;
        __syncthreads();
        for (int idx = t; idx < 8 * DIM; idx += 256) {
            int r = idx >> 9, d = idx & 511;
            int rr = rows[r] >= 0 ? rows[r] : rows[0];
            xs[r][d] = x[(size_t)rr * DIM + d];
        }
        __syncthreads();

        float bv[8]; int bi[8];
        #pragma unroll
        for (int r = 0; r < 8; r++) { bv[r] = FLT_MAX; bi[r] = 0; }

        for (int j = w; j < NE; j += 8) {
            const float4* er = (const float4*)(g_embT + (size_t)j * DIM);
            float a[8];
            #pragma unroll
            for (int r = 0; r < 8; r++) a[r] = 0.f;
            #pragma unroll
            for (int sub = 0; sub < 4; sub++) {
                float4 e = er[sub * 32 + lane];
                #pragma unroll
                for (int r = 0; r < 8; r++) {
                    const float4 xv = *(const float4*)&xs[r][sub * 128 + lane * 4];
                    a[r] = fmaf(e.x, xv.x, a[r]);
                    a[r] = fmaf(e.y, xv.y, a[r]);
                    a[r] = fmaf(e.z, xv.z, a[r]);
                    a[r] = fmaf(e.w, xv.w, a[r]);
                }
            }
            #pragma unroll
            for (int r = 0; r < 8; r++)
                #pragma unroll
                for (int o = 16; o > 0; o >>= 1)
                    a[r] += __shfl_xor_sync(0xffffffffu, a[r], o);
            float e2 = g_e2[j];
            #pragma unroll
            for (int r = 0; r < 8; r++) {
                float d = fmaf(-2.f, a[r], e2);
                if (d < bv[r]) { bv[r] = d; bi[r] = j; }
            }
        }
        if (lane == 0) {
            #pragma unroll
            for (int r = 0; r < 8; r++) { wv[w][r] = bv[r]; wi[w][r] = bi[r]; }
        }
        __syncthreads();
        if (t < 8) {
            int r = t;
            float fb = wv[0][r]; int fi = wi[0][r];
            #pragma unroll
            for (int q = 1; q < 8; q++) {
                if (wv[q][r] < fb || (wv[q][r] == fb && wi[q][r] < fi)) {
                    fb = wv[q][r]; fi = wi[q][r];
                }
            }
            if (g * 8 + r < n) g_best[rows[r]] = fi;
        }
    }
}

// ---------------- gather + diff ----------------
__global__ __launch_bounds__(128) void gather_kernel(
    const float* __restrict__ x, float* __restrict__ out)
{
    const int row = blockIdx.x;
    const int t = threadIdx.x;
    const int idx = g_best[row];
    const float4* q4 = (const float4*)(g_embT + (size_t)idx * DIM);
    const float4* x4 = (const float4*)(x + (size_t)row * DIM);
    float4* o4 = (float4*)(out + (size_t)row * DIM);

    float4 q = q4[t];
    float4 xv = x4[t];
    float dx = q.x - xv.x, dy = q.y - xv.y, dz = q.z - xv.z, dw = q.w - xv.w;
    float4 o;
    o.x = xv.x + dx; o.y = xv.y + dy; o.z = xv.z + dz; o.w = xv.w + dw;
    o4[t] = o;
    float s = dx * dx + dy * dy + dz * dz + dw * dw;

    __shared__ float red[128];
    red[t] = s;
    __syncthreads();
    #pragma unroll
    for (int off = 64; off > 0; off >>= 1) {
        if (t < off) red[t] += red[t + off];
        __syncthreads();
    }
    if (t == 0) {
        g_partial[row] = red[0];
        out[(size_t)NROWS * DIM + 1 + row] = (float)idx;
    }
}

__global__ void final_kernel(float* __restrict__ out) {
    __shared__ double red[256];
    int t = threadIdx.x;
    double s = 0.0;
    for (int i = t; i < NROWS; i += 256) s += (double)g_partial[i];
    red[t] = s;
    __syncthreads();
    for (int off = 128; off > 0; off >>= 1) {
        if (t < off) red[t] += red[t + off];
        __syncthreads();
    }
    if (t == 0)
        out[(size_t)NROWS * DIM] = (float)(red[0] / ((double)NROWS * (double)DIM));
}

// ----------------------------------------------------------------
extern "C" void kernel_launch(void* const* d_in, const int* in_sizes, int n_in,
                              void* d_out, int out_size) {
    const float* x     = (const float*)d_in[0];
    const float* embed = (const float*)d_in[1];
    float* out = (float*)d_out;

    cudaFuncSetAttribute(gemm_argmin_kernel,
                         cudaFuncAttributeMaxDynamicSharedMemorySize, SMEM_SZ);

    pack_x_kernel<<<NROWS * DIM / 4 / 256, 256>>>(x);
    pack_embed_kernel<<<dim3(NE / 32, DIM / 32), dim3(32, 8)>>>(embed);
    prep_e2<<<NE / 256, 256>>>(embed);
    gemm_argmin_kernel<<<NROWS / 128, NT, SMEM_SZ>>>();
    cand_kernel<<<2048, 256>>>(x);
    fixup_kernel<<<256, 256>>>();
    rescore_kernel<<<2048, 256>>>(x);
    gather_kernel<<<NROWS, 128>>>(x, out);
    final_kernel<<<1, 256>>>(out);
}